// round 15
// baseline (speedup 1.0000x reference)
#include <cuda_runtime.h>
#include <math.h>
#include <stdint.h>

#define BB 8192
#define IND 512
#define HIDD 2048
#define NCLS 1000
#define NE 4
#define KW1 16
#define KW2 64

// ---------------- device scratch ----------------
__device__ unsigned d_xbits[BB * KW1];
__device__ unsigned d_w1b[NE * HIDD * KW1];
__device__ unsigned d_w2b[NE * HIDD * KW2];
__device__ unsigned d_w3b[NE * NCLS * KW2];
__device__ short    d_hraw[(size_t)NE * BB * HIDD];
__device__ unsigned d_h1bits[NE * BB * KW2];
__device__ unsigned d_h2bits[NE * BB * KW2];
__device__ int      d_apop1[NE * BB];
__device__ int      d_apop2[NE * BB];
__device__ float    d_partial[3 * 512];
__device__ float    d_means[12];
__device__ float    d_gatew[BB * 2];
__device__ unsigned char d_slot[NE * BB];   // slot 0/1, 0xFF unselected
__device__ int      d_cnt[NE];
__device__ int      d_tok[NE * BB];
__device__ float    d_rh1[(size_t)BB * 256];
__device__ float    d_rh2[(size_t)BB * 128];

// ---------------- weight mean (deterministic 2-pass) ----------------
__global__ __launch_bounds__(256) void k_reduce(const float* __restrict__ W, int n_per_e, int m) {
    int e = blockIdx.x >> 7, blk = blockIdx.x & 127;
    size_t base = (size_t)e * n_per_e;
    int chunk = (n_per_e + 127) >> 7;
    int s = blk * chunk, en = min(s + chunk, n_per_e);
    float acc = 0.f;
    for (int i = s + (int)threadIdx.x; i < en; i += 256) acc += W[base + i];
    __shared__ float red[256];
    red[threadIdx.x] = acc; __syncthreads();
    for (int st = 128; st > 0; st >>= 1) {
        if ((int)threadIdx.x < st) red[threadIdx.x] += red[threadIdx.x + st];
        __syncthreads();
    }
    if (threadIdx.x == 0) d_partial[m * 512 + blockIdx.x] = red[0];
}

__global__ void k_means() {
    int t = threadIdx.x;
    if (t >= 12) return;
    int m = t >> 2, e = t & 3;
    float s = 0.f;
    for (int i = 0; i < 128; i++) s += d_partial[m * 512 + e * 128 + i];
    float n = (m == 0) ? 2048.f * 512.f : (m == 1 ? 2048.f * 2048.f : 1000.f * 2048.f);
    d_means[t] = s / n;
}

// ---------------- weight bit packing (coalesced ballot) ----------------
__global__ __launch_bounds__(256) void k_packw(const float* __restrict__ W, int moff,
                                               int words_per_e, int target, int total) {
    int gw = (blockIdx.x * 256 + threadIdx.x) >> 5;
    int lane = threadIdx.x & 31;
    int wbase = gw * 32;
    if (wbase >= total) return;
    int e = wbase / words_per_e;
    float mu = d_means[moff + e];
    const float* base = W + (size_t)wbase * 32;
    unsigned my = 0;
#pragma unroll
    for (int j = 0; j < 32; j++) {
        unsigned b = __ballot_sync(0xffffffffu, base[j * 32 + lane] > mu);
        if (lane == j) my = b;
    }
    unsigned* out = (target == 0) ? d_w1b : (target == 1 ? d_w2b : d_w3b);
    out[wbase + lane] = my;
}

__global__ __launch_bounds__(256) void k_packx(const float* __restrict__ x) {
    int gw = (blockIdx.x * 256 + threadIdx.x) >> 5;
    int lane = threadIdx.x & 31;
    int wbase = gw * 32;
    if (wbase >= BB * KW1) return;
    const float* base = x + (size_t)wbase * 32;
    unsigned my = 0;
#pragma unroll
    for (int j = 0; j < 32; j++) {
        unsigned b = __ballot_sync(0xffffffffu, base[j * 32 + lane] > 0.f);
        if (lane == j) my = b;
    }
    d_xbits[wbase + lane] = my;
}

// ---------------- router: register-blocked fp32 GEMM + relu ----------------
__global__ __launch_bounds__(256) void k_rgemm(const float* __restrict__ A,
                                               const float* __restrict__ W,
                                               const float* __restrict__ bias,
                                               float* __restrict__ out, int K, int N) {
    int m0 = blockIdx.x * 64, n0 = blockIdx.y * 64;
    __shared__ float As[16][68];
    __shared__ float Bs[16][68];
    int tid = threadIdx.x;
    int lr = tid >> 2, lk = (tid & 3) * 4;
    int tx = tid & 15, ty = tid >> 4;
    const float* Arow = A + (size_t)(m0 + lr) * K + lk;
    const float* Wrow = W + (size_t)(n0 + lr) * K + lk;
    float4 pa = *(const float4*)Arow;
    float4 pb = *(const float4*)Wrow;
    float acc[4][4];
#pragma unroll
    for (int i = 0; i < 4; i++)
#pragma unroll
        for (int j = 0; j < 4; j++) acc[i][j] = 0.f;
    int NCH = K / 16;
    for (int c = 0; c < NCH; c++) {
        As[lk + 0][lr] = pa.x; As[lk + 1][lr] = pa.y; As[lk + 2][lr] = pa.z; As[lk + 3][lr] = pa.w;
        Bs[lk + 0][lr] = pb.x; Bs[lk + 1][lr] = pb.y; Bs[lk + 2][lr] = pb.z; Bs[lk + 3][lr] = pb.w;
        __syncthreads();
        if (c + 1 < NCH) {
            pa = *(const float4*)(Arow + (c + 1) * 16);
            pb = *(const float4*)(Wrow + (c + 1) * 16);
        }
#pragma unroll
        for (int kk = 0; kk < 16; kk++) {
            float4 a4 = *(const float4*)&As[kk][ty * 4];
            float4 b4 = *(const float4*)&Bs[kk][tx * 4];
            float av[4] = {a4.x, a4.y, a4.z, a4.w};
            float bv[4] = {b4.x, b4.y, b4.z, b4.w};
#pragma unroll
            for (int i = 0; i < 4; i++)
#pragma unroll
                for (int j = 0; j < 4; j++) acc[i][j] = fmaf(av[i], bv[j], acc[i][j]);
        }
        __syncthreads();
    }
#pragma unroll
    for (int i = 0; i < 4; i++) {
        float4 o4;
        float* r = &o4.x;
#pragma unroll
        for (int j = 0; j < 4; j++) r[j] = fmaxf(acc[i][j] + bias[n0 + tx * 4 + j], 0.f);
        *(float4*)&out[(size_t)(m0 + ty * 4 + i) * N + n0 + tx * 4] = o4;
    }
}

// ---------------- router head: scores + softmax + top2 ----------------
__global__ __launch_bounds__(128) void k_r3(const float* __restrict__ Wr3,
                                            const float* __restrict__ br3) {
    __shared__ float ws[512];
    __shared__ float bs[4];
    int tid = threadIdx.x;
    for (int i = tid; i < 512; i += 128) ws[i] = Wr3[i];
    if (tid < 4) bs[tid] = br3[tid];
    __syncthreads();
    int w = tid >> 5, l = tid & 31;
    int t = blockIdx.x * 4 + w;
    float h[4];
#pragma unroll
    for (int j = 0; j < 4; j++) h[j] = d_rh2[(size_t)t * 128 + l + 32 * j];
    float s[4];
#pragma unroll
    for (int e = 0; e < 4; e++) {
        float v = h[0] * ws[e * 128 + l] + h[1] * ws[e * 128 + l + 32]
                + h[2] * ws[e * 128 + l + 64] + h[3] * ws[e * 128 + l + 96];
#pragma unroll
        for (int off = 16; off > 0; off >>= 1) v += __shfl_xor_sync(0xffffffffu, v, off);
        s[e] = v + bs[e];
    }
    if (l == 0) {
        float m = fmaxf(fmaxf(s[0], s[1]), fmaxf(s[2], s[3]));
        float p[4], Z = 0.f;
#pragma unroll
        for (int e = 0; e < 4; e++) { p[e] = expf(s[e] - m); Z += p[e]; }
        int i0 = 0;
        for (int e = 1; e < 4; e++) if (p[e] > p[i0]) i0 = e;
        int i1 = (i0 == 0) ? 1 : 0;
        for (int e = 0; e < 4; e++) { if (e == i0) continue; if (p[e] > p[i1]) i1 = e; }
        float g0 = p[i0] / Z, g1 = p[i1] / Z, gs = g0 + g1;
        d_gatew[t * 2] = g0 / gs; d_gatew[t * 2 + 1] = g1 / gs;
#pragma unroll
        for (int e = 0; e < 4; e++)
            d_slot[e * BB + t] = (e == i0) ? 0 : ((e == i1) ? 1 : 0xFF);
    }
}

// ---------------- deterministic per-expert compaction ----------------
__global__ __launch_bounds__(256) void k_compact() {
    int e = blockIdx.x, t = threadIdx.x;
    __shared__ int cnts[256];
    int base = t * 32, c = 0;
    for (int i = 0; i < 32; i++) if (d_slot[e * BB + base + i] != 0xFF) c++;
    cnts[t] = c; __syncthreads();
    for (int st = 1; st < 256; st <<= 1) {
        int v = (t >= st) ? cnts[t - st] : 0;
        __syncthreads();
        cnts[t] += v;
        __syncthreads();
    }
    int off = cnts[t] - c;
    for (int i = 0; i < 32; i++)
        if (d_slot[e * BB + base + i] != 0xFF) d_tok[e * BB + off++] = base + i;
    if (t == 255) d_cnt[e] = cnts[255];
}

// ---------------- CSA (carry-save) weighted popcount of 16 words ----------------
#define CSA(_s, _c, _x, _y, _z) { unsigned _u = (_x), _v = (_y), _w = (_z); \
    (_s) = _u ^ _v ^ _w; (_c) = (_u & _v) | (_w & (_u ^ _v)); }

__device__ __forceinline__ int wpopc16(const unsigned* w) {
    unsigned a0,b0,a1,b1,a2,b2,a3,b3,a4,b4;
    CSA(a0,b0, w[0],w[1],w[2]);  CSA(a1,b1, w[3],w[4],w[5]);
    CSA(a2,b2, w[6],w[7],w[8]);  CSA(a3,b3, w[9],w[10],w[11]);
    CSA(a4,b4, w[12],w[13],w[14]);
    unsigned a5,b5,a6,b6;
    CSA(a5,b5, a0,a1,a2);  CSA(a6,b6, a3,a4,w[15]);
    unsigned s2a,c4a,s2b,c4b,s2c,c4c;
    CSA(s2a,c4a, b0,b1,b2);  CSA(s2b,c4b, b3,b4,b5);
    CSA(s2c,c4c, s2a,s2b,b6);
    unsigned s4,c8;
    CSA(s4,c8, c4a,c4b,c4c);
    return __popc(a5) + __popc(a6) + 2*__popc(s2c) + 4*__popc(s4) + 8*__popc(c8);
}

// ---------------- layer1 binary GEMM (xor + CSA popc, 32 tok/block) ----------------
__global__ __launch_bounds__(256, 3) void k_gemm1() {
    __shared__ uint4 as_[32 * 4];
    int b0 = blockIdx.x * 32, o0 = blockIdx.y * 128, e = blockIdx.z;
    int cnt = d_cnt[e];
    if (b0 >= cnt) return;
    int tid = threadIdx.x;
    if (tid < 128) {
        int row = tid >> 2, q = tid & 3;
        int pos = min(b0 + row, cnt - 1);
        int tok = d_tok[e * BB + pos];
        as_[tid] = ((const uint4*)d_xbits)[tok * 4 + q];
    }
    __syncthreads();
    int o = tid & 127, t0 = (tid >> 7) * 16;
    const uint4* wr = (const uint4*)(d_w1b + ((size_t)e * HIDD + o0 + o) * KW1);
    uint4 w0 = wr[0], w1 = wr[1], w2 = wr[2], w3 = wr[3];
    int acc[16];
#pragma unroll
    for (int t = 0; t < 16; t++) {
        const uint4* a = &as_[(t0 + t) * 4];
        uint4 a0 = a[0], a1 = a[1], a2 = a[2], a3 = a[3];
        unsigned ww[16];
        ww[0]=a0.x^w0.x; ww[1]=a0.y^w0.y; ww[2]=a0.z^w0.z; ww[3]=a0.w^w0.w;
        ww[4]=a1.x^w1.x; ww[5]=a1.y^w1.y; ww[6]=a1.z^w1.z; ww[7]=a1.w^w1.w;
        ww[8]=a2.x^w2.x; ww[9]=a2.y^w2.y; ww[10]=a2.z^w2.z; ww[11]=a2.w^w2.w;
        ww[12]=a3.x^w3.x; ww[13]=a3.y^w3.y; ww[14]=a3.z^w3.z; ww[15]=a3.w^w3.w;
        acc[t] = wpopc16(ww);
    }
#pragma unroll
    for (int t = 0; t < 16; t++) {
        if (b0 + t0 + t < cnt)
            d_hraw[((size_t)e * BB + b0 + t0 + t) * HIDD + o0 + o] = (short)(512 - 2 * acc[t]);
    }
}

// ---------------- LayerNorm + relu + sign-pack (vectorized, exact stats) ----------------
__global__ __launch_bounds__(256) void k_ln(const float* __restrict__ g,
                                            const float* __restrict__ bt, int phase) {
    int e = blockIdx.y, pos = blockIdx.x;
    if (pos >= d_cnt[e]) return;
    size_t row = (size_t)e * BB + pos;
    int tid = threadIdx.x, lane = tid & 31, wp = tid >> 5;
    __shared__ int w_i[8];
    __shared__ long long w_q[8];
    __shared__ int spop;
    uint4 raw = ((const uint4*)(d_hraw + row * HIDD))[tid];
    short h[8];
    h[0] = (short)(raw.x & 0xffff); h[1] = (short)(raw.x >> 16);
    h[2] = (short)(raw.y & 0xffff); h[3] = (short)(raw.y >> 16);
    h[4] = (short)(raw.z & 0xffff); h[5] = (short)(raw.z >> 16);
    h[6] = (short)(raw.w & 0xffff); h[7] = (short)(raw.w >> 16);
    int isum = 0; long long isq = 0;
#pragma unroll
    for (int j = 0; j < 8; j++) { isum += h[j]; isq += (long long)h[j] * h[j]; }
#pragma unroll
    for (int off = 16; off > 0; off >>= 1) {
        isum += __shfl_xor_sync(0xffffffffu, isum, off);
        isq  += __shfl_xor_sync(0xffffffffu, isq, off);
    }
    if (lane == 0) { w_i[wp] = isum; w_q[wp] = isq; }
    if (tid == 0) spop = 0;
    __syncthreads();
    int ti = w_i[lane & 7];
    long long tq = w_q[lane & 7];
#pragma unroll
    for (int off = 4; off > 0; off >>= 1) {
        ti += __shfl_xor_sync(0xffffffffu, ti, off);
        tq += __shfl_xor_sync(0xffffffffu, tq, off);
    }
    double mu = (double)ti / 2048.0;
    double var = (double)tq / 2048.0 - mu * mu;
    float rs = (float)(1.0 / sqrt(var + 1e-5));
    float fmu = (float)mu;
    const float4* gp = (const float4*)(g + (size_t)e * HIDD) + tid * 2;
    const float4* bp = (const float4*)(bt + (size_t)e * HIDD) + tid * 2;
    float4 g0 = gp[0], g1 = gp[1], b0 = bp[0], b1 = bp[1];
    float gv[8] = {g0.x, g0.y, g0.z, g0.w, g1.x, g1.y, g1.z, g1.w};
    float bv[8] = {b0.x, b0.y, b0.z, b0.w, b1.x, b1.y, b1.z, b1.w};
    unsigned byte_ = 0;
#pragma unroll
    for (int j = 0; j < 8; j++) {
        float hn = ((float)h[j] - fmu) * rs;
        if (hn * gv[j] + bv[j] > 0.f) byte_ |= (1u << j);
    }
    int mypop = __popc(byte_);
    unsigned v = byte_ << ((tid & 3) * 8);
    v |= __shfl_xor_sync(0xffffffffu, v, 1);
    v |= __shfl_xor_sync(0xffffffffu, v, 2);
    unsigned* outb = (phase == 1) ? d_h1bits : d_h2bits;
    if ((lane & 3) == 0) outb[row * KW2 + (tid >> 2)] = v;
#pragma unroll
    for (int off = 16; off > 0; off >>= 1) mypop += __shfl_xor_sync(0xffffffffu, mypop, off);
    if (lane == 0) atomicAdd(&spop, mypop);
    __syncthreads();
    int* outp = (phase == 1) ? d_apop1 : d_apop2;
    if (tid == 0) outp[row] = spop;
}

// ---------------- layer2 GEMM (and + CSA popc, K-phased, 32 tok/block) ----------------
__global__ __launch_bounds__(256, 3) void k_gemm2() {
    __shared__ uint4 a4s[32 * 16];
    __shared__ int ap[32];
    int b0 = blockIdx.x * 32, o0 = blockIdx.y * 128, e = blockIdx.z;
    int cnt = d_cnt[e];
    if (b0 >= cnt) return;
    int tid = threadIdx.x;
#pragma unroll
    for (int r = 0; r < 2; r++) {
        int idx = tid + 256 * r;
        int row = idx >> 4, q = idx & 15;
        int pos = min(b0 + row, cnt - 1);
        a4s[idx] = ((const uint4*)d_h1bits)[((size_t)e * BB + pos) * 16 + q];
    }
    if (tid < 32) ap[tid] = d_apop1[(size_t)e * BB + min(b0 + tid, cnt - 1)];
    __syncthreads();
    int o = tid & 127, t0 = (tid >> 7) * 16;
    const uint4* wr = (const uint4*)(d_w2b + ((size_t)e * HIDD + o0 + o) * KW2);
    int acc[16];
#pragma unroll
    for (int t = 0; t < 16; t++) acc[t] = 0;
#pragma unroll
    for (int p = 0; p < 4; p++) {
        uint4 w0 = wr[p * 4 + 0], w1 = wr[p * 4 + 1], w2 = wr[p * 4 + 2], w3 = wr[p * 4 + 3];
#pragma unroll
        for (int t = 0; t < 16; t++) {
            const uint4* a = &a4s[(t0 + t) * 16 + p * 4];
            uint4 a0 = a[0], a1 = a[1], a2 = a[2], a3 = a[3];
            unsigned ww[16];
            ww[0]=a0.x&w0.x; ww[1]=a0.y&w0.y; ww[2]=a0.z&w0.z; ww[3]=a0.w&w0.w;
            ww[4]=a1.x&w1.x; ww[5]=a1.y&w1.y; ww[6]=a1.z&w1.z; ww[7]=a1.w&w1.w;
            ww[8]=a2.x&w2.x; ww[9]=a2.y&w2.y; ww[10]=a2.z&w2.z; ww[11]=a2.w&w2.w;
            ww[12]=a3.x&w3.x; ww[13]=a3.y&w3.y; ww[14]=a3.z&w3.z; ww[15]=a3.w&w3.w;
            acc[t] += wpopc16(ww);
        }
    }
#pragma unroll
    for (int t = 0; t < 16; t++) {
        if (b0 + t0 + t < cnt)
            d_hraw[((size_t)e * BB + b0 + t0 + t) * HIDD + o0 + o] =
                (short)(2 * acc[t] - ap[t0 + t]);
    }
}

// ---------------- layer3 GEMM: fused gate + atomicAdd into out ----------------
__global__ __launch_bounds__(256, 3) void k_gemm3(float* __restrict__ out) {
    __shared__ uint4 a4s[32 * 16];
    __shared__ int ap[32];
    __shared__ int ts[32];
    __shared__ float gv[32];
    int b0 = blockIdx.x * 32, c0 = blockIdx.y * 128, e = blockIdx.z;
    int cnt = d_cnt[e];
    if (b0 >= cnt) return;
    int tid = threadIdx.x;
#pragma unroll
    for (int r = 0; r < 2; r++) {
        int idx = tid + 256 * r;
        int row = idx >> 4, q = idx & 15;
        int pos = min(b0 + row, cnt - 1);
        a4s[idx] = ((const uint4*)d_h2bits)[((size_t)e * BB + pos) * 16 + q];
    }
    if (tid < 32) {
        int pos = min(b0 + tid, cnt - 1);
        ap[tid] = d_apop2[(size_t)e * BB + pos];
        int tok = d_tok[e * BB + pos];
        ts[tid] = tok;
        int sl = d_slot[e * BB + tok];
        gv[tid] = d_gatew[tok * 2 + sl];
    }
    __syncthreads();
    int c = c0 + (tid & 127), t0 = (tid >> 7) * 16;
    if (c >= NCLS) return;
    const uint4* wr = (const uint4*)(d_w3b + ((size_t)e * NCLS + c) * KW2);
    int acc[16];
#pragma unroll
    for (int t = 0; t < 16; t++) acc[t] = 0;
#pragma unroll
    for (int p = 0; p < 4; p++) {
        uint4 w0 = wr[p * 4 + 0], w1 = wr[p * 4 + 1], w2 = wr[p * 4 + 2], w3 = wr[p * 4 + 3];
#pragma unroll
        for (int t = 0; t < 16; t++) {
            const uint4* a = &a4s[(t0 + t) * 16 + p * 4];
            uint4 a0 = a[0], a1 = a[1], a2 = a[2], a3 = a[3];
            unsigned ww[16];
            ww[0]=a0.x&w0.x; ww[1]=a0.y&w0.y; ww[2]=a0.z&w0.z; ww[3]=a0.w&w0.w;
            ww[4]=a1.x&w1.x; ww[5]=a1.y&w1.y; ww[6]=a1.z&w1.z; ww[7]=a1.w&w1.w;
            ww[8]=a2.x&w2.x; ww[9]=a2.y&w2.y; ww[10]=a2.z&w2.z; ww[11]=a2.w&w2.w;
            ww[12]=a3.x&w3.x; ww[13]=a3.y&w3.y; ww[14]=a3.z&w3.z; ww[15]=a3.w&w3.w;
            acc[t] += wpopc16(ww);
        }
    }
#pragma unroll
    for (int t = 0; t < 16; t++) {
        if (b0 + t0 + t < cnt) {
            float dot = (float)(2 * acc[t] - ap[t0 + t]);
            atomicAdd(&out[(size_t)ts[t0 + t] * NCLS + c], gv[t0 + t] * dot);
        }
    }
}

extern "C" void kernel_launch(void* const* d_in, const int* in_sizes, int n_in,
                              void* d_out, int out_size) {
    const float* x   = (const float*)d_in[0];
    const float* Wr1 = (const float*)d_in[1];
    const float* br1 = (const float*)d_in[2];
    const float* Wr2 = (const float*)d_in[3];
    const float* br2 = (const float*)d_in[4];
    const float* Wr3 = (const float*)d_in[5];
    const float* br3 = (const float*)d_in[6];
    const float* W1  = (const float*)d_in[7];
    const float* g1  = (const float*)d_in[8];
    const float* b1  = (const float*)d_in[9];
    const float* W2  = (const float*)d_in[10];
    const float* g2  = (const float*)d_in[11];
    const float* b2  = (const float*)d_in[12];
    const float* W3  = (const float*)d_in[13];
    float* out = (float*)d_out;

    float* rh1; cudaGetSymbolAddress((void**)&rh1, d_rh1);
    float* rh2; cudaGetSymbolAddress((void**)&rh2, d_rh2);

    cudaMemsetAsync(out, 0, (size_t)out_size * sizeof(float));
    k_reduce<<<512, 256>>>(W1, HIDD * IND, 0);
    k_reduce<<<512, 256>>>(W2, HIDD * HIDD, 1);
    k_reduce<<<512, 256>>>(W3, NCLS * HIDD, 2);
    k_rgemm<<<dim3(BB / 64, 4), 256>>>(x, Wr1, br1, rh1, 512, 256);
    k_means<<<1, 32>>>();
    k_packw<<<NE * HIDD * KW1 / 256, 256>>>(W1, 0, HIDD * KW1, 0, NE * HIDD * KW1);
    k_packw<<<NE * HIDD * KW2 / 256, 256>>>(W2, 4, HIDD * KW2, 1, NE * HIDD * KW2);
    k_packw<<<NE * NCLS * KW2 / 256, 256>>>(W3, 8, NCLS * KW2, 2, NE * NCLS * KW2);
    k_packx<<<BB * KW1 / 256, 256>>>(x);
    k_rgemm<<<dim3(BB / 64, 2), 256>>>(rh1, Wr2, br2, rh2, 256, 128);
    k_r3<<<BB / 4, 128>>>(Wr3, br3);
    k_compact<<<NE, 256>>>();
    k_gemm1<<<dim3(BB / 32, HIDD / 128, NE), 256>>>();
    k_ln<<<dim3(BB, NE), 256>>>(g1, b1, 1);
    k_gemm2<<<dim3(BB / 32, HIDD / 128, NE), 256>>>();
    k_ln<<<dim3(BB, NE), 256>>>(g2, b2, 2);
    k_gemm3<<<dim3(BB / 32, (NCLS + 127) / 128, NE), 256>>>(out);
}

// round 16
// speedup vs baseline: 1.0293x; 1.0293x over previous
#include <cuda_runtime.h>
#include <math.h>
#include <stdint.h>

#define BB 8192
#define IND 512
#define HIDD 2048
#define NCLS 1000
#define NE 4
#define KW1 16
#define KW2 64

// ---------------- device scratch ----------------
__device__ unsigned d_xbits[BB * KW1];
__device__ unsigned d_w1b[NE * HIDD * KW1];
__device__ unsigned d_w2b[NE * HIDD * KW2];
__device__ unsigned d_w3b[NE * NCLS * KW2];
__device__ short    d_hraw[(size_t)NE * BB * HIDD];
__device__ unsigned d_h1bits[NE * BB * KW2];
__device__ unsigned d_h2bits[NE * BB * KW2];
__device__ int      d_apop1[NE * BB];
__device__ int      d_apop2[NE * BB];
__device__ short    d_eo[(size_t)BB * 2 * NCLS];
__device__ float    d_partial[3 * 512];
__device__ float    d_means[12];
__device__ float    d_gatew[BB * 2];
__device__ unsigned char d_slot[NE * BB];   // slot 0/1, 0xFF unselected
__device__ int      d_cnt[NE];
__device__ int      d_tok[NE * BB];
__device__ float    d_rh1[(size_t)BB * 256];
__device__ float    d_rh2[(size_t)BB * 128];

// ---------------- weight mean (deterministic 2-pass) ----------------
__global__ __launch_bounds__(256) void k_reduce(const float* __restrict__ W, int n_per_e, int m) {
    int e = blockIdx.x >> 7, blk = blockIdx.x & 127;
    size_t base = (size_t)e * n_per_e;
    int chunk = (n_per_e + 127) >> 7;
    int s = blk * chunk, en = min(s + chunk, n_per_e);
    float acc = 0.f;
    for (int i = s + (int)threadIdx.x; i < en; i += 256) acc += W[base + i];
    __shared__ float red[256];
    red[threadIdx.x] = acc; __syncthreads();
    for (int st = 128; st > 0; st >>= 1) {
        if ((int)threadIdx.x < st) red[threadIdx.x] += red[threadIdx.x + st];
        __syncthreads();
    }
    if (threadIdx.x == 0) d_partial[m * 512 + blockIdx.x] = red[0];
}

__global__ void k_means() {
    int t = threadIdx.x;
    if (t >= 12) return;
    int m = t >> 2, e = t & 3;
    float s = 0.f;
    for (int i = 0; i < 128; i++) s += d_partial[m * 512 + e * 128 + i];
    float n = (m == 0) ? 2048.f * 512.f : (m == 1 ? 2048.f * 2048.f : 1000.f * 2048.f);
    d_means[t] = s / n;
}

// ---------------- weight bit packing (coalesced ballot) ----------------
__global__ __launch_bounds__(256) void k_packw(const float* __restrict__ W, int moff,
                                               int words_per_e, int target, int total) {
    int gw = (blockIdx.x * 256 + threadIdx.x) >> 5;
    int lane = threadIdx.x & 31;
    int wbase = gw * 32;
    if (wbase >= total) return;
    int e = wbase / words_per_e;
    float mu = d_means[moff + e];
    const float* base = W + (size_t)wbase * 32;
    unsigned my = 0;
#pragma unroll
    for (int j = 0; j < 32; j++) {
        unsigned b = __ballot_sync(0xffffffffu, base[j * 32 + lane] > mu);
        if (lane == j) my = b;
    }
    unsigned* out = (target == 0) ? d_w1b : (target == 1 ? d_w2b : d_w3b);
    out[wbase + lane] = my;
}

__global__ __launch_bounds__(256) void k_packx(const float* __restrict__ x) {
    int gw = (blockIdx.x * 256 + threadIdx.x) >> 5;
    int lane = threadIdx.x & 31;
    int wbase = gw * 32;
    if (wbase >= BB * KW1) return;
    const float* base = x + (size_t)wbase * 32;
    unsigned my = 0;
#pragma unroll
    for (int j = 0; j < 32; j++) {
        unsigned b = __ballot_sync(0xffffffffu, base[j * 32 + lane] > 0.f);
        if (lane == j) my = b;
    }
    d_xbits[wbase + lane] = my;
}

// ---------------- router: 128x128-tile fp32 GEMM + relu, 8x8/thread ----------------
__global__ __launch_bounds__(256) void k_rgemm(const float* __restrict__ A,
                                               const float* __restrict__ W,
                                               const float* __restrict__ bias,
                                               float* __restrict__ out, int K, int N) {
    int m0 = blockIdx.x * 128, n0 = blockIdx.y * 128;
    __shared__ float As[16][132];
    __shared__ float Bs[16][132];
    int tid = threadIdx.x;
    int lr = tid >> 1, lk = (tid & 1) * 8;
    int tx = tid & 15, ty = tid >> 4;
    const float* Arow = A + (size_t)(m0 + lr) * K + lk;
    const float* Wrow = W + (size_t)(n0 + lr) * K + lk;
    float4 pa0 = ((const float4*)Arow)[0], pa1 = ((const float4*)Arow)[1];
    float4 pb0 = ((const float4*)Wrow)[0], pb1 = ((const float4*)Wrow)[1];
    float acc[8][8];
#pragma unroll
    for (int i = 0; i < 8; i++)
#pragma unroll
        for (int j = 0; j < 8; j++) acc[i][j] = 0.f;
    int NCH = K / 16;
    for (int c = 0; c < NCH; c++) {
        As[lk + 0][lr] = pa0.x; As[lk + 1][lr] = pa0.y; As[lk + 2][lr] = pa0.z; As[lk + 3][lr] = pa0.w;
        As[lk + 4][lr] = pa1.x; As[lk + 5][lr] = pa1.y; As[lk + 6][lr] = pa1.z; As[lk + 7][lr] = pa1.w;
        Bs[lk + 0][lr] = pb0.x; Bs[lk + 1][lr] = pb0.y; Bs[lk + 2][lr] = pb0.z; Bs[lk + 3][lr] = pb0.w;
        Bs[lk + 4][lr] = pb1.x; Bs[lk + 5][lr] = pb1.y; Bs[lk + 6][lr] = pb1.z; Bs[lk + 7][lr] = pb1.w;
        __syncthreads();
        if (c + 1 < NCH) {
            const float4* pA = (const float4*)(Arow + (c + 1) * 16);
            const float4* pW = (const float4*)(Wrow + (c + 1) * 16);
            pa0 = pA[0]; pa1 = pA[1];
            pb0 = pW[0]; pb1 = pW[1];
        }
#pragma unroll
        for (int kk = 0; kk < 16; kk++) {
            float4 a0 = *(const float4*)&As[kk][ty * 8];
            float4 a1 = *(const float4*)&As[kk][ty * 8 + 4];
            float4 b0 = *(const float4*)&Bs[kk][tx * 8];
            float4 b1 = *(const float4*)&Bs[kk][tx * 8 + 4];
            float av[8] = {a0.x, a0.y, a0.z, a0.w, a1.x, a1.y, a1.z, a1.w};
            float bv[8] = {b0.x, b0.y, b0.z, b0.w, b1.x, b1.y, b1.z, b1.w};
#pragma unroll
            for (int i = 0; i < 8; i++)
#pragma unroll
                for (int j = 0; j < 8; j++) acc[i][j] = fmaf(av[i], bv[j], acc[i][j]);
        }
        __syncthreads();
    }
#pragma unroll
    for (int i = 0; i < 8; i++) {
        float4 o0, o1;
        float* r0 = &o0.x; float* r1 = &o1.x;
#pragma unroll
        for (int j = 0; j < 4; j++) {
            r0[j] = fmaxf(acc[i][j] + bias[n0 + tx * 8 + j], 0.f);
            r1[j] = fmaxf(acc[i][j + 4] + bias[n0 + tx * 8 + 4 + j], 0.f);
        }
        float* orow = &out[(size_t)(m0 + ty * 8 + i) * N + n0 + tx * 8];
        *(float4*)orow = o0;
        *(float4*)(orow + 4) = o1;
    }
}

// ---------------- router head: scores + softmax + top2 ----------------
__global__ __launch_bounds__(128) void k_r3(const float* __restrict__ Wr3,
                                            const float* __restrict__ br3) {
    __shared__ float ws[512];
    __shared__ float bs[4];
    int tid = threadIdx.x;
    for (int i = tid; i < 512; i += 128) ws[i] = Wr3[i];
    if (tid < 4) bs[tid] = br3[tid];
    __syncthreads();
    int w = tid >> 5, l = tid & 31;
    int t = blockIdx.x * 4 + w;
    float h[4];
#pragma unroll
    for (int j = 0; j < 4; j++) h[j] = d_rh2[(size_t)t * 128 + l + 32 * j];
    float s[4];
#pragma unroll
    for (int e = 0; e < 4; e++) {
        float v = h[0] * ws[e * 128 + l] + h[1] * ws[e * 128 + l + 32]
                + h[2] * ws[e * 128 + l + 64] + h[3] * ws[e * 128 + l + 96];
#pragma unroll
        for (int off = 16; off > 0; off >>= 1) v += __shfl_xor_sync(0xffffffffu, v, off);
        s[e] = v + bs[e];
    }
    if (l == 0) {
        float m = fmaxf(fmaxf(s[0], s[1]), fmaxf(s[2], s[3]));
        float p[4], Z = 0.f;
#pragma unroll
        for (int e = 0; e < 4; e++) { p[e] = expf(s[e] - m); Z += p[e]; }
        int i0 = 0;
        for (int e = 1; e < 4; e++) if (p[e] > p[i0]) i0 = e;
        int i1 = (i0 == 0) ? 1 : 0;
        for (int e = 0; e < 4; e++) { if (e == i0) continue; if (p[e] > p[i1]) i1 = e; }
        float g0 = p[i0] / Z, g1 = p[i1] / Z, gs = g0 + g1;
        d_gatew[t * 2] = g0 / gs; d_gatew[t * 2 + 1] = g1 / gs;
#pragma unroll
        for (int e = 0; e < 4; e++)
            d_slot[e * BB + t] = (e == i0) ? 0 : ((e == i1) ? 1 : 0xFF);
    }
}

// ---------------- deterministic per-expert compaction ----------------
__global__ __launch_bounds__(256) void k_compact() {
    int e = blockIdx.x, t = threadIdx.x;
    __shared__ int cnts[256];
    int base = t * 32, c = 0;
    for (int i = 0; i < 32; i++) if (d_slot[e * BB + base + i] != 0xFF) c++;
    cnts[t] = c; __syncthreads();
    for (int st = 1; st < 256; st <<= 1) {
        int v = (t >= st) ? cnts[t - st] : 0;
        __syncthreads();
        cnts[t] += v;
        __syncthreads();
    }
    int off = cnts[t] - c;
    for (int i = 0; i < 32; i++)
        if (d_slot[e * BB + base + i] != 0xFF) d_tok[e * BB + off++] = base + i;
    if (t == 255) d_cnt[e] = cnts[255];
}

// ---------------- CSA (carry-save) weighted popcount of 16 words ----------------
#define CSA(_s, _c, _x, _y, _z) { unsigned _u = (_x), _v = (_y), _w = (_z); \
    (_s) = _u ^ _v ^ _w; (_c) = (_u & _v) | (_w & (_u ^ _v)); }

__device__ __forceinline__ int wpopc16(const unsigned* w) {
    unsigned a0,b0,a1,b1,a2,b2,a3,b3,a4,b4;
    CSA(a0,b0, w[0],w[1],w[2]);  CSA(a1,b1, w[3],w[4],w[5]);
    CSA(a2,b2, w[6],w[7],w[8]);  CSA(a3,b3, w[9],w[10],w[11]);
    CSA(a4,b4, w[12],w[13],w[14]);
    unsigned a5,b5,a6,b6;
    CSA(a5,b5, a0,a1,a2);  CSA(a6,b6, a3,a4,w[15]);
    unsigned s2a,c4a,s2b,c4b,s2c,c4c;
    CSA(s2a,c4a, b0,b1,b2);  CSA(s2b,c4b, b3,b4,b5);
    CSA(s2c,c4c, s2a,s2b,b6);
    unsigned s4,c8;
    CSA(s4,c8, c4a,c4b,c4c);
    return __popc(a5) + __popc(a6) + 2*__popc(s2c) + 4*__popc(s4) + 8*__popc(c8);
}

// ---------------- layer1 binary GEMM (xor + CSA popc, 32 tok/block) ----------------
__global__ __launch_bounds__(256, 3) void k_gemm1() {
    __shared__ uint4 as_[32 * 4];
    int b0 = blockIdx.x * 32, o0 = blockIdx.y * 128, e = blockIdx.z;
    int cnt = d_cnt[e];
    if (b0 >= cnt) return;
    int tid = threadIdx.x;
    if (tid < 128) {
        int row = tid >> 2, q = tid & 3;
        int pos = min(b0 + row, cnt - 1);
        int tok = d_tok[e * BB + pos];
        as_[tid] = ((const uint4*)d_xbits)[tok * 4 + q];
    }
    __syncthreads();
    int o = tid & 127, t0 = (tid >> 7) * 16;
    const uint4* wr = (const uint4*)(d_w1b + ((size_t)e * HIDD + o0 + o) * KW1);
    uint4 w0 = wr[0], w1 = wr[1], w2 = wr[2], w3 = wr[3];
    int acc[16];
#pragma unroll
    for (int t = 0; t < 16; t++) {
        const uint4* a = &as_[(t0 + t) * 4];
        uint4 a0 = a[0], a1 = a[1], a2 = a[2], a3 = a[3];
        unsigned ww[16];
        ww[0]=a0.x^w0.x; ww[1]=a0.y^w0.y; ww[2]=a0.z^w0.z; ww[3]=a0.w^w0.w;
        ww[4]=a1.x^w1.x; ww[5]=a1.y^w1.y; ww[6]=a1.z^w1.z; ww[7]=a1.w^w1.w;
        ww[8]=a2.x^w2.x; ww[9]=a2.y^w2.y; ww[10]=a2.z^w2.z; ww[11]=a2.w^w2.w;
        ww[12]=a3.x^w3.x; ww[13]=a3.y^w3.y; ww[14]=a3.z^w3.z; ww[15]=a3.w^w3.w;
        acc[t] = wpopc16(ww);
    }
#pragma unroll
    for (int t = 0; t < 16; t++) {
        if (b0 + t0 + t < cnt)
            d_hraw[((size_t)e * BB + b0 + t0 + t) * HIDD + o0 + o] = (short)(512 - 2 * acc[t]);
    }
}

// ---------------- LayerNorm + relu + sign-pack (vectorized, exact stats) ----------------
__global__ __launch_bounds__(256) void k_ln(const float* __restrict__ g,
                                            const float* __restrict__ bt, int phase) {
    int e = blockIdx.y, pos = blockIdx.x;
    if (pos >= d_cnt[e]) return;
    size_t row = (size_t)e * BB + pos;
    int tid = threadIdx.x, lane = tid & 31, wp = tid >> 5;
    __shared__ int w_i[8];
    __shared__ long long w_q[8];
    __shared__ int spop;
    uint4 raw = ((const uint4*)(d_hraw + row * HIDD))[tid];
    short h[8];
    h[0] = (short)(raw.x & 0xffff); h[1] = (short)(raw.x >> 16);
    h[2] = (short)(raw.y & 0xffff); h[3] = (short)(raw.y >> 16);
    h[4] = (short)(raw.z & 0xffff); h[5] = (short)(raw.z >> 16);
    h[6] = (short)(raw.w & 0xffff); h[7] = (short)(raw.w >> 16);
    int isum = 0; long long isq = 0;
#pragma unroll
    for (int j = 0; j < 8; j++) { isum += h[j]; isq += (long long)h[j] * h[j]; }
#pragma unroll
    for (int off = 16; off > 0; off >>= 1) {
        isum += __shfl_xor_sync(0xffffffffu, isum, off);
        isq  += __shfl_xor_sync(0xffffffffu, isq, off);
    }
    if (lane == 0) { w_i[wp] = isum; w_q[wp] = isq; }
    if (tid == 0) spop = 0;
    __syncthreads();
    int ti = w_i[lane & 7];
    long long tq = w_q[lane & 7];
#pragma unroll
    for (int off = 4; off > 0; off >>= 1) {
        ti += __shfl_xor_sync(0xffffffffu, ti, off);
        tq += __shfl_xor_sync(0xffffffffu, tq, off);
    }
    double mu = (double)ti / 2048.0;
    double var = (double)tq / 2048.0 - mu * mu;
    float rs = (float)(1.0 / sqrt(var + 1e-5));
    float fmu = (float)mu;
    const float4* gp = (const float4*)(g + (size_t)e * HIDD) + tid * 2;
    const float4* bp = (const float4*)(bt + (size_t)e * HIDD) + tid * 2;
    float4 g0 = gp[0], g1 = gp[1], b0 = bp[0], b1 = bp[1];
    float gv[8] = {g0.x, g0.y, g0.z, g0.w, g1.x, g1.y, g1.z, g1.w};
    float bv[8] = {b0.x, b0.y, b0.z, b0.w, b1.x, b1.y, b1.z, b1.w};
    unsigned byte_ = 0;
#pragma unroll
    for (int j = 0; j < 8; j++) {
        float hn = ((float)h[j] - fmu) * rs;
        if (hn * gv[j] + bv[j] > 0.f) byte_ |= (1u << j);
    }
    int mypop = __popc(byte_);
    unsigned v = byte_ << ((tid & 3) * 8);
    v |= __shfl_xor_sync(0xffffffffu, v, 1);
    v |= __shfl_xor_sync(0xffffffffu, v, 2);
    unsigned* outb = (phase == 1) ? d_h1bits : d_h2bits;
    if ((lane & 3) == 0) outb[row * KW2 + (tid >> 2)] = v;
#pragma unroll
    for (int off = 16; off > 0; off >>= 1) mypop += __shfl_xor_sync(0xffffffffu, mypop, off);
    if (lane == 0) atomicAdd(&spop, mypop);
    __syncthreads();
    int* outp = (phase == 1) ? d_apop1 : d_apop2;
    if (tid == 0) outp[row] = spop;
}

// ---------------- layer2 GEMM (and + CSA popc, K-phased, 32 tok/block) ----------------
__global__ __launch_bounds__(256, 3) void k_gemm2() {
    __shared__ uint4 a4s[32 * 16];
    __shared__ int ap[32];
    int b0 = blockIdx.x * 32, o0 = blockIdx.y * 128, e = blockIdx.z;
    int cnt = d_cnt[e];
    if (b0 >= cnt) return;
    int tid = threadIdx.x;
#pragma unroll
    for (int r = 0; r < 2; r++) {
        int idx = tid + 256 * r;
        int row = idx >> 4, q = idx & 15;
        int pos = min(b0 + row, cnt - 1);
        a4s[idx] = ((const uint4*)d_h1bits)[((size_t)e * BB + pos) * 16 + q];
    }
    if (tid < 32) ap[tid] = d_apop1[(size_t)e * BB + min(b0 + tid, cnt - 1)];
    __syncthreads();
    int o = tid & 127, t0 = (tid >> 7) * 16;
    const uint4* wr = (const uint4*)(d_w2b + ((size_t)e * HIDD + o0 + o) * KW2);
    int acc[16];
#pragma unroll
    for (int t = 0; t < 16; t++) acc[t] = 0;
#pragma unroll
    for (int p = 0; p < 4; p++) {
        uint4 w0 = wr[p * 4 + 0], w1 = wr[p * 4 + 1], w2 = wr[p * 4 + 2], w3 = wr[p * 4 + 3];
#pragma unroll
        for (int t = 0; t < 16; t++) {
            const uint4* a = &a4s[(t0 + t) * 16 + p * 4];
            uint4 a0 = a[0], a1 = a[1], a2 = a[2], a3 = a[3];
            unsigned ww[16];
            ww[0]=a0.x&w0.x; ww[1]=a0.y&w0.y; ww[2]=a0.z&w0.z; ww[3]=a0.w&w0.w;
            ww[4]=a1.x&w1.x; ww[5]=a1.y&w1.y; ww[6]=a1.z&w1.z; ww[7]=a1.w&w1.w;
            ww[8]=a2.x&w2.x; ww[9]=a2.y&w2.y; ww[10]=a2.z&w2.z; ww[11]=a2.w&w2.w;
            ww[12]=a3.x&w3.x; ww[13]=a3.y&w3.y; ww[14]=a3.z&w3.z; ww[15]=a3.w&w3.w;
            acc[t] += wpopc16(ww);
        }
    }
#pragma unroll
    for (int t = 0; t < 16; t++) {
        if (b0 + t0 + t < cnt)
            d_hraw[((size_t)e * BB + b0 + t0 + t) * HIDD + o0 + o] =
                (short)(2 * acc[t] - ap[t0 + t]);
    }
}

// ---------------- layer3 GEMM -> per-slot dots (and + CSA popc, scatter) ----------------
__global__ __launch_bounds__(256, 3) void k_gemm3() {
    __shared__ uint4 a4s[32 * 16];
    __shared__ int ap[32];
    __shared__ int ts[32];
    __shared__ unsigned char ss[32];
    int b0 = blockIdx.x * 32, c0 = blockIdx.y * 128, e = blockIdx.z;
    int cnt = d_cnt[e];
    if (b0 >= cnt) return;
    int tid = threadIdx.x;
#pragma unroll
    for (int r = 0; r < 2; r++) {
        int idx = tid + 256 * r;
        int row = idx >> 4, q = idx & 15;
        int pos = min(b0 + row, cnt - 1);
        a4s[idx] = ((const uint4*)d_h2bits)[((size_t)e * BB + pos) * 16 + q];
    }
    if (tid < 32) {
        int pos = min(b0 + tid, cnt - 1);
        ap[tid] = d_apop2[(size_t)e * BB + pos];
        int tok = d_tok[e * BB + pos];
        ts[tid] = tok;
        ss[tid] = d_slot[e * BB + tok];
    }
    __syncthreads();
    int c = c0 + (tid & 127), t0 = (tid >> 7) * 16;
    if (c >= NCLS) return;
    const uint4* wr = (const uint4*)(d_w3b + ((size_t)e * NCLS + c) * KW2);
    int acc[16];
#pragma unroll
    for (int t = 0; t < 16; t++) acc[t] = 0;
#pragma unroll
    for (int p = 0; p < 4; p++) {
        uint4 w0 = wr[p * 4 + 0], w1 = wr[p * 4 + 1], w2 = wr[p * 4 + 2], w3 = wr[p * 4 + 3];
#pragma unroll
        for (int t = 0; t < 16; t++) {
            const uint4* a = &a4s[(t0 + t) * 16 + p * 4];
            uint4 a0 = a[0], a1 = a[1], a2 = a[2], a3 = a[3];
            unsigned ww[16];
            ww[0]=a0.x&w0.x; ww[1]=a0.y&w0.y; ww[2]=a0.z&w0.z; ww[3]=a0.w&w0.w;
            ww[4]=a1.x&w1.x; ww[5]=a1.y&w1.y; ww[6]=a1.z&w1.z; ww[7]=a1.w&w1.w;
            ww[8]=a2.x&w2.x; ww[9]=a2.y&w2.y; ww[10]=a2.z&w2.z; ww[11]=a2.w&w2.w;
            ww[12]=a3.x&w3.x; ww[13]=a3.y&w3.y; ww[14]=a3.z&w3.z; ww[15]=a3.w&w3.w;
            acc[t] += wpopc16(ww);
        }
    }
#pragma unroll
    for (int t = 0; t < 16; t++) {
        if (b0 + t0 + t < cnt)
            d_eo[((size_t)(ts[t0 + t] * 2 + ss[t0 + t])) * NCLS + c] =
                (short)(2 * acc[t] - ap[t0 + t]);
    }
}

// ---------------- gate combine ----------------
__global__ __launch_bounds__(256) void k_combine(float* __restrict__ out) {
    int i = blockIdx.x * 256 + threadIdx.x;
    if (i >= BB * NCLS) return;
    int b = i / NCLS, c = i - b * NCLS;
    out[i] = d_gatew[b * 2] * (float)d_eo[(size_t)(b * 2) * NCLS + c]
           + d_gatew[b * 2 + 1] * (float)d_eo[(size_t)(b * 2 + 1) * NCLS + c];
}

extern "C" void kernel_launch(void* const* d_in, const int* in_sizes, int n_in,
                              void* d_out, int out_size) {
    const float* x   = (const float*)d_in[0];
    const float* Wr1 = (const float*)d_in[1];
    const float* br1 = (const float*)d_in[2];
    const float* Wr2 = (const float*)d_in[3];
    const float* br2 = (const float*)d_in[4];
    const float* Wr3 = (const float*)d_in[5];
    const float* br3 = (const float*)d_in[6];
    const float* W1  = (const float*)d_in[7];
    const float* g1  = (const float*)d_in[8];
    const float* b1  = (const float*)d_in[9];
    const float* W2  = (const float*)d_in[10];
    const float* g2  = (const float*)d_in[11];
    const float* b2  = (const float*)d_in[12];
    const float* W3  = (const float*)d_in[13];
    float* out = (float*)d_out;

    float* rh1; cudaGetSymbolAddress((void**)&rh1, d_rh1);
    float* rh2; cudaGetSymbolAddress((void**)&rh2, d_rh2);

    k_reduce<<<512, 256>>>(W1, HIDD * IND, 0);
    k_reduce<<<512, 256>>>(W2, HIDD * HIDD, 1);
    k_reduce<<<512, 256>>>(W3, NCLS * HIDD, 2);
    k_rgemm<<<dim3(BB / 128, 2), 256>>>(x, Wr1, br1, rh1, 512, 256);
    k_means<<<1, 32>>>();
    k_packw<<<NE * HIDD * KW1 / 256, 256>>>(W1, 0, HIDD * KW1, 0, NE * HIDD * KW1);
    k_packw<<<NE * HIDD * KW2 / 256, 256>>>(W2, 4, HIDD * KW2, 1, NE * HIDD * KW2);
    k_packw<<<NE * NCLS * KW2 / 256, 256>>>(W3, 8, NCLS * KW2, 2, NE * NCLS * KW2);
    k_packx<<<BB * KW1 / 256, 256>>>(x);
    k_rgemm<<<dim3(BB / 128, 1), 256>>>(rh1, Wr2, br2, rh2, 256, 128);
    k_r3<<<BB / 4, 128>>>(Wr3, br3);
    k_compact<<<NE, 256>>>();
    k_gemm1<<<dim3(BB / 32, HIDD / 128, NE), 256>>>();
    k_ln<<<dim3(BB, NE), 256>>>(g1, b1, 1);
    k_gemm2<<<dim3(BB / 32, HIDD / 128, NE), 256>>>();
    k_ln<<<dim3(BB, NE), 256>>>(g2, b2, 2);
    k_gemm3<<<dim3(BB / 32, (NCLS + 127) / 128, NE), 256>>>();
    k_combine<<<(BB * NCLS + 255) / 256, 256>>>(out);
}

// round 17
// speedup vs baseline: 1.0378x; 1.0082x over previous
#include <cuda_runtime.h>
#include <math.h>
#include <stdint.h>

#define BB 8192
#define IND 512
#define HIDD 2048
#define NCLS 1000
#define NE 4
#define KW1 16
#define KW2 64

// ---------------- device scratch ----------------
__device__ unsigned d_xbits[BB * KW1];
__device__ unsigned d_w1b[NE * HIDD * KW1];
__device__ unsigned d_w2b[NE * HIDD * KW2];
__device__ unsigned d_w3b[NE * NCLS * KW2];
__device__ short    d_hraw[(size_t)NE * BB * HIDD];
__device__ unsigned d_h1bits[NE * BB * KW2];
__device__ unsigned d_h2bits[NE * BB * KW2];
__device__ int      d_apop1[NE * BB];
__device__ int      d_apop2[NE * BB];
__device__ short    d_eo[(size_t)BB * 2 * NCLS];
__device__ float    d_partial[3 * 512];
__device__ float    d_means[12];
__device__ float    d_gatew[BB * 2];
__device__ unsigned char d_slot[NE * BB];   // slot 0/1, 0xFF unselected
__device__ int      d_cnt[NE];
__device__ int      d_tok[NE * BB];
__device__ float    d_rh1[(size_t)BB * 256];
__device__ float    d_rh2[(size_t)BB * 128];

// ---------------- weight mean (deterministic 2-pass) ----------------
__global__ __launch_bounds__(256) void k_reduce(const float* __restrict__ W, int n_per_e, int m) {
    int e = blockIdx.x >> 7, blk = blockIdx.x & 127;
    size_t base = (size_t)e * n_per_e;
    int chunk = (n_per_e + 127) >> 7;
    int s = blk * chunk, en = min(s + chunk, n_per_e);
    float acc = 0.f;
    for (int i = s + (int)threadIdx.x; i < en; i += 256) acc += W[base + i];
    __shared__ float red[256];
    red[threadIdx.x] = acc; __syncthreads();
    for (int st = 128; st > 0; st >>= 1) {
        if ((int)threadIdx.x < st) red[threadIdx.x] += red[threadIdx.x + st];
        __syncthreads();
    }
    if (threadIdx.x == 0) d_partial[m * 512 + blockIdx.x] = red[0];
}

__global__ void k_means() {
    int t = threadIdx.x;
    if (t >= 12) return;
    int m = t >> 2, e = t & 3;
    float s = 0.f;
    for (int i = 0; i < 128; i++) s += d_partial[m * 512 + e * 128 + i];
    float n = (m == 0) ? 2048.f * 512.f : (m == 1 ? 2048.f * 2048.f : 1000.f * 2048.f);
    d_means[t] = s / n;
}

// ---------------- weight bit packing (coalesced ballot) ----------------
__global__ __launch_bounds__(256) void k_packw(const float* __restrict__ W, int moff,
                                               int words_per_e, int target, int total) {
    int gw = (blockIdx.x * 256 + threadIdx.x) >> 5;
    int lane = threadIdx.x & 31;
    int wbase = gw * 32;
    if (wbase >= total) return;
    int e = wbase / words_per_e;
    float mu = d_means[moff + e];
    const float* base = W + (size_t)wbase * 32;
    unsigned my = 0;
#pragma unroll
    for (int j = 0; j < 32; j++) {
        unsigned b = __ballot_sync(0xffffffffu, base[j * 32 + lane] > mu);
        if (lane == j) my = b;
    }
    unsigned* out = (target == 0) ? d_w1b : (target == 1 ? d_w2b : d_w3b);
    out[wbase + lane] = my;
}

__global__ __launch_bounds__(256) void k_packx(const float* __restrict__ x) {
    int gw = (blockIdx.x * 256 + threadIdx.x) >> 5;
    int lane = threadIdx.x & 31;
    int wbase = gw * 32;
    if (wbase >= BB * KW1) return;
    const float* base = x + (size_t)wbase * 32;
    unsigned my = 0;
#pragma unroll
    for (int j = 0; j < 32; j++) {
        unsigned b = __ballot_sync(0xffffffffu, base[j * 32 + lane] > 0.f);
        if (lane == j) my = b;
    }
    d_xbits[wbase + lane] = my;
}

// ---------------- router: 128x64-tile fp32 GEMM + relu, 8x4/thread ----------------
__global__ __launch_bounds__(256) void k_rgemm(const float* __restrict__ A,
                                               const float* __restrict__ W,
                                               const float* __restrict__ bias,
                                               float* __restrict__ out, int K, int N) {
    int m0 = blockIdx.x * 128, n0 = blockIdx.y * 64;
    __shared__ float As[16][132];
    __shared__ float Bs[16][68];
    int tid = threadIdx.x;
    int lrA = tid >> 1, lkA = (tid & 1) * 8;
    int lrB = tid >> 2, lkB = (tid & 3) * 4;
    int tx = tid & 15, ty = tid >> 4;
    const float* Arow = A + (size_t)(m0 + lrA) * K + lkA;
    const float* Wrow = W + (size_t)(n0 + lrB) * K + lkB;
    float4 pa0 = ((const float4*)Arow)[0], pa1 = ((const float4*)Arow)[1];
    float4 pb = *(const float4*)Wrow;
    float acc[8][4];
#pragma unroll
    for (int i = 0; i < 8; i++)
#pragma unroll
        for (int j = 0; j < 4; j++) acc[i][j] = 0.f;
    int NCH = K / 16;
    for (int c = 0; c < NCH; c++) {
        As[lkA + 0][lrA] = pa0.x; As[lkA + 1][lrA] = pa0.y; As[lkA + 2][lrA] = pa0.z; As[lkA + 3][lrA] = pa0.w;
        As[lkA + 4][lrA] = pa1.x; As[lkA + 5][lrA] = pa1.y; As[lkA + 6][lrA] = pa1.z; As[lkA + 7][lrA] = pa1.w;
        Bs[lkB + 0][lrB] = pb.x; Bs[lkB + 1][lrB] = pb.y; Bs[lkB + 2][lrB] = pb.z; Bs[lkB + 3][lrB] = pb.w;
        __syncthreads();
        if (c + 1 < NCH) {
            const float4* pA = (const float4*)(Arow + (c + 1) * 16);
            pa0 = pA[0]; pa1 = pA[1];
            pb = *(const float4*)(Wrow + (c + 1) * 16);
        }
#pragma unroll
        for (int kk = 0; kk < 16; kk++) {
            float4 a0 = *(const float4*)&As[kk][ty * 8];
            float4 a1 = *(const float4*)&As[kk][ty * 8 + 4];
            float4 b0 = *(const float4*)&Bs[kk][tx * 4];
            float av[8] = {a0.x, a0.y, a0.z, a0.w, a1.x, a1.y, a1.z, a1.w};
            float bv[4] = {b0.x, b0.y, b0.z, b0.w};
#pragma unroll
            for (int i = 0; i < 8; i++)
#pragma unroll
                for (int j = 0; j < 4; j++) acc[i][j] = fmaf(av[i], bv[j], acc[i][j]);
        }
        __syncthreads();
    }
#pragma unroll
    for (int i = 0; i < 8; i++) {
        float4 o;
        float* r = &o.x;
#pragma unroll
        for (int j = 0; j < 4; j++)
            r[j] = fmaxf(acc[i][j] + bias[n0 + tx * 4 + j], 0.f);
        *(float4*)&out[(size_t)(m0 + ty * 8 + i) * N + n0 + tx * 4] = o;
    }
}

// ---------------- router head: scores + softmax + top2 ----------------
__global__ __launch_bounds__(128) void k_r3(const float* __restrict__ Wr3,
                                            const float* __restrict__ br3) {
    __shared__ float ws[512];
    __shared__ float bs[4];
    int tid = threadIdx.x;
    for (int i = tid; i < 512; i += 128) ws[i] = Wr3[i];
    if (tid < 4) bs[tid] = br3[tid];
    __syncthreads();
    int w = tid >> 5, l = tid & 31;
    int t = blockIdx.x * 4 + w;
    float h[4];
#pragma unroll
    for (int j = 0; j < 4; j++) h[j] = d_rh2[(size_t)t * 128 + l + 32 * j];
    float s[4];
#pragma unroll
    for (int e = 0; e < 4; e++) {
        float v = h[0] * ws[e * 128 + l] + h[1] * ws[e * 128 + l + 32]
                + h[2] * ws[e * 128 + l + 64] + h[3] * ws[e * 128 + l + 96];
#pragma unroll
        for (int off = 16; off > 0; off >>= 1) v += __shfl_xor_sync(0xffffffffu, v, off);
        s[e] = v + bs[e];
    }
    if (l == 0) {
        float m = fmaxf(fmaxf(s[0], s[1]), fmaxf(s[2], s[3]));
        float p[4], Z = 0.f;
#pragma unroll
        for (int e = 0; e < 4; e++) { p[e] = expf(s[e] - m); Z += p[e]; }
        int i0 = 0;
        for (int e = 1; e < 4; e++) if (p[e] > p[i0]) i0 = e;
        int i1 = (i0 == 0) ? 1 : 0;
        for (int e = 0; e < 4; e++) { if (e == i0) continue; if (p[e] > p[i1]) i1 = e; }
        float g0 = p[i0] / Z, g1 = p[i1] / Z, gs = g0 + g1;
        d_gatew[t * 2] = g0 / gs; d_gatew[t * 2 + 1] = g1 / gs;
#pragma unroll
        for (int e = 0; e < 4; e++)
            d_slot[e * BB + t] = (e == i0) ? 0 : ((e == i1) ? 1 : 0xFF);
    }
}

// ---------------- deterministic per-expert compaction ----------------
__global__ __launch_bounds__(256) void k_compact() {
    int e = blockIdx.x, t = threadIdx.x;
    __shared__ int cnts[256];
    int base = t * 32, c = 0;
    for (int i = 0; i < 32; i++) if (d_slot[e * BB + base + i] != 0xFF) c++;
    cnts[t] = c; __syncthreads();
    for (int st = 1; st < 256; st <<= 1) {
        int v = (t >= st) ? cnts[t - st] : 0;
        __syncthreads();
        cnts[t] += v;
        __syncthreads();
    }
    int off = cnts[t] - c;
    for (int i = 0; i < 32; i++)
        if (d_slot[e * BB + base + i] != 0xFF) d_tok[e * BB + off++] = base + i;
    if (t == 255) d_cnt[e] = cnts[255];
}

// ---------------- CSA (carry-save) weighted popcount of 16 words ----------------
#define CSA(_s, _c, _x, _y, _z) { unsigned _u = (_x), _v = (_y), _w = (_z); \
    (_s) = _u ^ _v ^ _w; (_c) = (_u & _v) | (_w & (_u ^ _v)); }

__device__ __forceinline__ int wpopc16(const unsigned* w) {
    unsigned a0,b0,a1,b1,a2,b2,a3,b3,a4,b4;
    CSA(a0,b0, w[0],w[1],w[2]);  CSA(a1,b1, w[3],w[4],w[5]);
    CSA(a2,b2, w[6],w[7],w[8]);  CSA(a3,b3, w[9],w[10],w[11]);
    CSA(a4,b4, w[12],w[13],w[14]);
    unsigned a5,b5,a6,b6;
    CSA(a5,b5, a0,a1,a2);  CSA(a6,b6, a3,a4,w[15]);
    unsigned s2a,c4a,s2b,c4b,s2c,c4c;
    CSA(s2a,c4a, b0,b1,b2);  CSA(s2b,c4b, b3,b4,b5);
    CSA(s2c,c4c, s2a,s2b,b6);
    unsigned s4,c8;
    CSA(s4,c8, c4a,c4b,c4c);
    return __popc(a5) + __popc(a6) + 2*__popc(s2c) + 4*__popc(s4) + 8*__popc(c8);
}

// ---------------- layer1 binary GEMM (xor + CSA popc, 32 tok/block) ----------------
__global__ __launch_bounds__(256, 3) void k_gemm1() {
    __shared__ uint4 as_[32 * 4];
    int b0 = blockIdx.x * 32, o0 = blockIdx.y * 128, e = blockIdx.z;
    int cnt = d_cnt[e];
    if (b0 >= cnt) return;
    int tid = threadIdx.x;
    if (tid < 128) {
        int row = tid >> 2, q = tid & 3;
        int pos = min(b0 + row, cnt - 1);
        int tok = d_tok[e * BB + pos];
        as_[tid] = ((const uint4*)d_xbits)[tok * 4 + q];
    }
    __syncthreads();
    int o = tid & 127, t0 = (tid >> 7) * 16;
    const uint4* wr = (const uint4*)(d_w1b + ((size_t)e * HIDD + o0 + o) * KW1);
    uint4 w0 = wr[0], w1 = wr[1], w2 = wr[2], w3 = wr[3];
    int acc[16];
#pragma unroll
    for (int t = 0; t < 16; t++) {
        const uint4* a = &as_[(t0 + t) * 4];
        uint4 a0 = a[0], a1 = a[1], a2 = a[2], a3 = a[3];
        unsigned ww[16];
        ww[0]=a0.x^w0.x; ww[1]=a0.y^w0.y; ww[2]=a0.z^w0.z; ww[3]=a0.w^w0.w;
        ww[4]=a1.x^w1.x; ww[5]=a1.y^w1.y; ww[6]=a1.z^w1.z; ww[7]=a1.w^w1.w;
        ww[8]=a2.x^w2.x; ww[9]=a2.y^w2.y; ww[10]=a2.z^w2.z; ww[11]=a2.w^w2.w;
        ww[12]=a3.x^w3.x; ww[13]=a3.y^w3.y; ww[14]=a3.z^w3.z; ww[15]=a3.w^w3.w;
        acc[t] = wpopc16(ww);
    }
#pragma unroll
    for (int t = 0; t < 16; t++) {
        if (b0 + t0 + t < cnt)
            d_hraw[((size_t)e * BB + b0 + t0 + t) * HIDD + o0 + o] = (short)(512 - 2 * acc[t]);
    }
}

// ---------------- LayerNorm + relu + sign-pack (vectorized, exact stats) ----------------
__global__ __launch_bounds__(256) void k_ln(const float* __restrict__ g,
                                            const float* __restrict__ bt, int phase) {
    int e = blockIdx.y, pos = blockIdx.x;
    if (pos >= d_cnt[e]) return;
    size_t row = (size_t)e * BB + pos;
    int tid = threadIdx.x, lane = tid & 31, wp = tid >> 5;
    __shared__ int w_i[8];
    __shared__ long long w_q[8];
    __shared__ int spop;
    uint4 raw = ((const uint4*)(d_hraw + row * HIDD))[tid];
    short h[8];
    h[0] = (short)(raw.x & 0xffff); h[1] = (short)(raw.x >> 16);
    h[2] = (short)(raw.y & 0xffff); h[3] = (short)(raw.y >> 16);
    h[4] = (short)(raw.z & 0xffff); h[5] = (short)(raw.z >> 16);
    h[6] = (short)(raw.w & 0xffff); h[7] = (short)(raw.w >> 16);
    int isum = 0; long long isq = 0;
#pragma unroll
    for (int j = 0; j < 8; j++) { isum += h[j]; isq += (long long)h[j] * h[j]; }
#pragma unroll
    for (int off = 16; off > 0; off >>= 1) {
        isum += __shfl_xor_sync(0xffffffffu, isum, off);
        isq  += __shfl_xor_sync(0xffffffffu, isq, off);
    }
    if (lane == 0) { w_i[wp] = isum; w_q[wp] = isq; }
    if (tid == 0) spop = 0;
    __syncthreads();
    int ti = w_i[lane & 7];
    long long tq = w_q[lane & 7];
#pragma unroll
    for (int off = 4; off > 0; off >>= 1) {
        ti += __shfl_xor_sync(0xffffffffu, ti, off);
        tq += __shfl_xor_sync(0xffffffffu, tq, off);
    }
    double mu = (double)ti / 2048.0;
    double var = (double)tq / 2048.0 - mu * mu;
    float rs = (float)(1.0 / sqrt(var + 1e-5));
    float fmu = (float)mu;
    const float4* gp = (const float4*)(g + (size_t)e * HIDD) + tid * 2;
    const float4* bp = (const float4*)(bt + (size_t)e * HIDD) + tid * 2;
    float4 g0 = gp[0], g1 = gp[1], b0 = bp[0], b1 = bp[1];
    float gv[8] = {g0.x, g0.y, g0.z, g0.w, g1.x, g1.y, g1.z, g1.w};
    float bv[8] = {b0.x, b0.y, b0.z, b0.w, b1.x, b1.y, b1.z, b1.w};
    unsigned byte_ = 0;
#pragma unroll
    for (int j = 0; j < 8; j++) {
        float hn = ((float)h[j] - fmu) * rs;
        if (hn * gv[j] + bv[j] > 0.f) byte_ |= (1u << j);
    }
    int mypop = __popc(byte_);
    unsigned v = byte_ << ((tid & 3) * 8);
    v |= __shfl_xor_sync(0xffffffffu, v, 1);
    v |= __shfl_xor_sync(0xffffffffu, v, 2);
    unsigned* outb = (phase == 1) ? d_h1bits : d_h2bits;
    if ((lane & 3) == 0) outb[row * KW2 + (tid >> 2)] = v;
#pragma unroll
    for (int off = 16; off > 0; off >>= 1) mypop += __shfl_xor_sync(0xffffffffu, mypop, off);
    if (lane == 0) atomicAdd(&spop, mypop);
    __syncthreads();
    int* outp = (phase == 1) ? d_apop1 : d_apop2;
    if (tid == 0) outp[row] = spop;
}

// ---------------- layer2 GEMM (and + CSA popc, K-phased, 32 tok/block) ----------------
__global__ __launch_bounds__(256, 3) void k_gemm2() {
    __shared__ uint4 a4s[32 * 16];
    __shared__ int ap[32];
    int b0 = blockIdx.x * 32, o0 = blockIdx.y * 128, e = blockIdx.z;
    int cnt = d_cnt[e];
    if (b0 >= cnt) return;
    int tid = threadIdx.x;
#pragma unroll
    for (int r = 0; r < 2; r++) {
        int idx = tid + 256 * r;
        int row = idx >> 4, q = idx & 15;
        int pos = min(b0 + row, cnt - 1);
        a4s[idx] = ((const uint4*)d_h1bits)[((size_t)e * BB + pos) * 16 + q];
    }
    if (tid < 32) ap[tid] = d_apop1[(size_t)e * BB + min(b0 + tid, cnt - 1)];
    __syncthreads();
    int o = tid & 127, t0 = (tid >> 7) * 16;
    const uint4* wr = (const uint4*)(d_w2b + ((size_t)e * HIDD + o0 + o) * KW2);
    int acc[16];
#pragma unroll
    for (int t = 0; t < 16; t++) acc[t] = 0;
#pragma unroll
    for (int p = 0; p < 4; p++) {
        uint4 w0 = wr[p * 4 + 0], w1 = wr[p * 4 + 1], w2 = wr[p * 4 + 2], w3 = wr[p * 4 + 3];
#pragma unroll
        for (int t = 0; t < 16; t++) {
            const uint4* a = &a4s[(t0 + t) * 16 + p * 4];
            uint4 a0 = a[0], a1 = a[1], a2 = a[2], a3 = a[3];
            unsigned ww[16];
            ww[0]=a0.x&w0.x; ww[1]=a0.y&w0.y; ww[2]=a0.z&w0.z; ww[3]=a0.w&w0.w;
            ww[4]=a1.x&w1.x; ww[5]=a1.y&w1.y; ww[6]=a1.z&w1.z; ww[7]=a1.w&w1.w;
            ww[8]=a2.x&w2.x; ww[9]=a2.y&w2.y; ww[10]=a2.z&w2.z; ww[11]=a2.w&w2.w;
            ww[12]=a3.x&w3.x; ww[13]=a3.y&w3.y; ww[14]=a3.z&w3.z; ww[15]=a3.w&w3.w;
            acc[t] += wpopc16(ww);
        }
    }
#pragma unroll
    for (int t = 0; t < 16; t++) {
        if (b0 + t0 + t < cnt)
            d_hraw[((size_t)e * BB + b0 + t0 + t) * HIDD + o0 + o] =
                (short)(2 * acc[t] - ap[t0 + t]);
    }
}

// ---------------- layer3 GEMM -> per-slot dots (and + CSA popc, scatter) ----------------
__global__ __launch_bounds__(256, 3) void k_gemm3() {
    __shared__ uint4 a4s[32 * 16];
    __shared__ int ap[32];
    __shared__ int ts[32];
    __shared__ unsigned char ss[32];
    int b0 = blockIdx.x * 32, c0 = blockIdx.y * 128, e = blockIdx.z;
    int cnt = d_cnt[e];
    if (b0 >= cnt) return;
    int tid = threadIdx.x;
#pragma unroll
    for (int r = 0; r < 2; r++) {
        int idx = tid + 256 * r;
        int row = idx >> 4, q = idx & 15;
        int pos = min(b0 + row, cnt - 1);
        a4s[idx] = ((const uint4*)d_h2bits)[((size_t)e * BB + pos) * 16 + q];
    }
    if (tid < 32) {
        int pos = min(b0 + tid, cnt - 1);
        ap[tid] = d_apop2[(size_t)e * BB + pos];
        int tok = d_tok[e * BB + pos];
        ts[tid] = tok;
        ss[tid] = d_slot[e * BB + tok];
    }
    __syncthreads();
    int c = c0 + (tid & 127), t0 = (tid >> 7) * 16;
    if (c >= NCLS) return;
    const uint4* wr = (const uint4*)(d_w3b + ((size_t)e * NCLS + c) * KW2);
    int acc[16];
#pragma unroll
    for (int t = 0; t < 16; t++) acc[t] = 0;
#pragma unroll
    for (int p = 0; p < 4; p++) {
        uint4 w0 = wr[p * 4 + 0], w1 = wr[p * 4 + 1], w2 = wr[p * 4 + 2], w3 = wr[p * 4 + 3];
#pragma unroll
        for (int t = 0; t < 16; t++) {
            const uint4* a = &a4s[(t0 + t) * 16 + p * 4];
            uint4 a0 = a[0], a1 = a[1], a2 = a[2], a3 = a[3];
            unsigned ww[16];
            ww[0]=a0.x&w0.x; ww[1]=a0.y&w0.y; ww[2]=a0.z&w0.z; ww[3]=a0.w&w0.w;
            ww[4]=a1.x&w1.x; ww[5]=a1.y&w1.y; ww[6]=a1.z&w1.z; ww[7]=a1.w&w1.w;
            ww[8]=a2.x&w2.x; ww[9]=a2.y&w2.y; ww[10]=a2.z&w2.z; ww[11]=a2.w&w2.w;
            ww[12]=a3.x&w3.x; ww[13]=a3.y&w3.y; ww[14]=a3.z&w3.z; ww[15]=a3.w&w3.w;
            acc[t] += wpopc16(ww);
        }
    }
#pragma unroll
    for (int t = 0; t < 16; t++) {
        if (b0 + t0 + t < cnt)
            d_eo[((size_t)(ts[t0 + t] * 2 + ss[t0 + t])) * NCLS + c] =
                (short)(2 * acc[t] - ap[t0 + t]);
    }
}

// ---------------- gate combine ----------------
__global__ __launch_bounds__(256) void k_combine(float* __restrict__ out) {
    int i = blockIdx.x * 256 + threadIdx.x;
    if (i >= BB * NCLS) return;
    int b = i / NCLS, c = i - b * NCLS;
    out[i] = d_gatew[b * 2] * (float)d_eo[(size_t)(b * 2) * NCLS + c]
           + d_gatew[b * 2 + 1] * (float)d_eo[(size_t)(b * 2 + 1) * NCLS + c];
}

extern "C" void kernel_launch(void* const* d_in, const int* in_sizes, int n_in,
                              void* d_out, int out_size) {
    const float* x   = (const float*)d_in[0];
    const float* Wr1 = (const float*)d_in[1];
    const float* br1 = (const float*)d_in[2];
    const float* Wr2 = (const float*)d_in[3];
    const float* br2 = (const float*)d_in[4];
    const float* Wr3 = (const float*)d_in[5];
    const float* br3 = (const float*)d_in[6];
    const float* W1  = (const float*)d_in[7];
    const float* g1  = (const float*)d_in[8];
    const float* b1  = (const float*)d_in[9];
    const float* W2  = (const float*)d_in[10];
    const float* g2  = (const float*)d_in[11];
    const float* b2  = (const float*)d_in[12];
    const float* W3  = (const float*)d_in[13];
    float* out = (float*)d_out;

    float* rh1; cudaGetSymbolAddress((void**)&rh1, d_rh1);
    float* rh2; cudaGetSymbolAddress((void**)&rh2, d_rh2);

    k_reduce<<<512, 256>>>(W1, HIDD * IND, 0);
    k_reduce<<<512, 256>>>(W2, HIDD * HIDD, 1);
    k_reduce<<<512, 256>>>(W3, NCLS * HIDD, 2);
    k_rgemm<<<dim3(BB / 128, 4), 256>>>(x, Wr1, br1, rh1, 512, 256);
    k_means<<<1, 32>>>();
    k_packw<<<NE * HIDD * KW1 / 256, 256>>>(W1, 0, HIDD * KW1, 0, NE * HIDD * KW1);
    k_packw<<<NE * HIDD * KW2 / 256, 256>>>(W2, 4, HIDD * KW2, 1, NE * HIDD * KW2);
    k_packw<<<NE * NCLS * KW2 / 256, 256>>>(W3, 8, NCLS * KW2, 2, NE * NCLS * KW2);
    k_packx<<<BB * KW1 / 256, 256>>>(x);
    k_rgemm<<<dim3(BB / 128, 2), 256>>>(rh1, Wr2, br2, rh2, 256, 128);
    k_r3<<<BB / 4, 128>>>(Wr3, br3);
    k_compact<<<NE, 256>>>();
    k_gemm1<<<dim3(BB / 32, HIDD / 128, NE), 256>>>();
    k_ln<<<dim3(BB, NE), 256>>>(g1, b1, 1);
    k_gemm2<<<dim3(BB / 32, HIDD / 128, NE), 256>>>();
    k_ln<<<dim3(BB, NE), 256>>>(g2, b2, 2);
    k_gemm3<<<dim3(BB / 32, (NCLS + 127) / 128, NE), 256>>>();
    k_combine<<<(BB * NCLS + 255) / 256, 256>>>(out);
}